// round 9
// baseline (speedup 1.0000x reference)
#include <cuda_runtime.h>

// Shapes fixed by the problem's setup_inputs.
#define B_      16
#define N_      1024
#define M_      1024
#define CIN_    7
#define C_      8
#define COUT_   16
#define TM_     128    // m-values per block: 32 lanes x 4 m-slots
#define THREADS_ 512   // 16 warps, each owns 32 n-pairs (64 n's)
#define NWARP_  16
#define PAIRS_W_ 32    // n-pairs per warp
#define EPS_    1e-8f

typedef unsigned long long ull;

__device__ __forceinline__ float ex2f(float v) {
    float r; asm("ex2.approx.f32 %0, %1;" : "=f"(r) : "f"(v)); return r;
}
__device__ __forceinline__ ull pack2(float lo, float hi) {
    ull r; asm("mov.b64 %0, {%1, %2};" : "=l"(r) : "f"(lo), "f"(hi)); return r;
}
__device__ __forceinline__ void unpack2(ull v, float& lo, float& hi) {
    asm("mov.b64 {%0, %1}, %2;" : "=f"(lo), "=f"(hi) : "l"(v));
}
__device__ __forceinline__ ull fma2(ull a, ull b, ull c) {
    ull d; asm("fma.rn.f32x2 %0, %1, %2, %3;" : "=l"(d) : "l"(a), "l"(b), "l"(c));
    return d;
}
__device__ __forceinline__ ull add2(ull a, ull b) {
    ull d; asm("add.rn.f32x2 %0, %1, %2;" : "=l"(d) : "l"(a), "l"(b));
    return d;
}

// Shared memory (static), with aliasing:
//   [0,      8192)  sxq: 512 ull2 {x0,x1 | q0,q1} per n-pair
//   [8192,  24576)  syA: 1024 ull2 {1,y0 | y1,y2} per n
//   [24576, 40960)  syB: 1024 ull2 {y3,y4 | y5,y6} per n
//   [0,     32768)  sacc: reduction scratch (ALIASES tile; used post-loop)
//   [40960, 41536)  sw (128 floats) + sb (16 floats)
#define SMEM_BYTES (40960 + 576)

__global__ __launch_bounds__(THREADS_, 1)
void convdeepset_kernel(const float* __restrict__ x,     // [B, N]
                        const float* __restrict__ y,     // [B, N, CIN]
                        const float* __restrict__ t,     // [B, M]
                        const float* __restrict__ sigma, // [C]
                        const float* __restrict__ w,     // [COUT, C]
                        const float* __restrict__ bias,  // [COUT]
                        float* __restrict__ out)         // [B, M, COUT]
{
    __shared__ __align__(16) char smem_raw[SMEM_BYTES];
    ulonglong2* sxq  = (ulonglong2*)smem_raw;              // [512]
    ulonglong2* syA  = (ulonglong2*)(smem_raw + 8192);     // [1024]
    ulonglong2* syB  = (ulonglong2*)(smem_raw + 24576);    // [1024]
    ulonglong2* sacc = (ulonglong2*)smem_raw;              // aliased, post-loop
    float*      sw   = (float*)(smem_raw + 40960);
    float*      sb   = sw + COUT_ * C_;

    const int b    = blockIdx.y;
    const int m0   = blockIdx.x * TM_;
    const int tid  = threadIdx.x;
    const int wrp  = tid >> 5;
    const int lane = tid & 31;

    if (tid < COUT_ * C_)                sw[tid] = w[tid];
    if (tid >= 128 && tid < 128 + COUT_) sb[tid - 128] = bias[tid - 128];

    // Per-channel exponent coefficient, log2e folded: arg = k2*(x-t)^2
    const float LOG2E = 1.4426950408889634f;
    const float s0 = expf(sigma[0]);
    const float k20 = -(0.5f * LOG2E) / (s0 * s0);
    bool uniform = true;
#pragma unroll
    for (int c = 1; c < C_; c++) {
        float s = expf(sigma[c]);
        uniform &= ((-(0.5f * LOG2E) / (s * s)) == k20);
    }

    // 4 m's per lane: m = m0 + s*32 + lane
    float tm[4];
    ull UU[4], TT[4];
#pragma unroll
    for (int s = 0; s < 4; s++) {
        tm[s] = t[b * M_ + m0 + s * 32 + lane];
        float Us = -2.0f * k20 * tm[s];
        float Ts = k20 * tm[s] * tm[s];
        UU[s] = pack2(Us, Us);
        TT[s] = pack2(Ts, Ts);
    }

    const float* xb  = x + b * N_;
    const float* ybp = y + (size_t)b * N_ * CIN_;

    // ---- Coalesced tile load: thread tid owns n-pair p = tid ----
    {
        const int p = tid;
        const float2 xv = ((const float2*)xb)[p];          // {x(2p), x(2p+1)}
        sxq[p] = make_ulonglong2(pack2(xv.x, xv.y),
                                 pack2(k20 * xv.x * xv.x, k20 * xv.y * xv.y));
        // 14 consecutive floats of y as 7 aligned float2 loads
        const float2* y2 = (const float2*)(ybp + (size_t)(2 * p) * CIN_);
        float2 f0 = y2[0], f1 = y2[1], f2 = y2[2], f3 = y2[3];
        float2 f4 = y2[4], f5 = y2[5], f6 = y2[6];
        // n0: a0..a6 = f0.x f0.y f1.x f1.y f2.x f2.y f3.x
        // n1: b0..b6 = f3.y f4.x f4.y f5.x f5.y f6.x f6.y
        syA[2 * p]     = make_ulonglong2(pack2(1.0f, f0.x), pack2(f0.y, f1.x));
        syB[2 * p]     = make_ulonglong2(pack2(f1.y, f2.x), pack2(f2.y, f3.x));
        syA[2 * p + 1] = make_ulonglong2(pack2(1.0f, f3.y), pack2(f4.x, f4.y));
        syB[2 * p + 1] = make_ulonglong2(pack2(f5.x, f5.y), pack2(f6.x, f6.y));
    }
    __syncthreads();

    // Accumulators: acc[m-slot][channel-pair]
    ull acc[4][4];
#pragma unroll
    for (int s = 0; s < 4; s++)
#pragma unroll
        for (int k = 0; k < 4; k++) acc[s][k] = 0ull;

    const int Pb = wrp * PAIRS_W_;   // this warp's first n-pair

    if (uniform) {
#pragma unroll 2
        for (int jj = 0; jj < PAIRS_W_; jj++) {
            const int P = Pb + jj;
            ulonglong2 v  = sxq[P];                 // {x0,x1 | q0,q1}
            ulonglong2 A0 = syA[2 * P], B0 = syB[2 * P];
            ulonglong2 A1 = syA[2 * P + 1], B1 = syB[2 * P + 1];
#pragma unroll
            for (int s = 0; s < 4; s++) {
                ull args = add2(fma2(UU[s], v.x, TT[s]), v.y);
                float f0, f1; unpack2(args, f0, f1);
                float e0 = ex2f(f0), e1 = ex2f(f1);
                ull ee0 = pack2(e0, e0);
                acc[s][0] = fma2(A0.x, ee0, acc[s][0]);
                acc[s][1] = fma2(A0.y, ee0, acc[s][1]);
                acc[s][2] = fma2(B0.x, ee0, acc[s][2]);
                acc[s][3] = fma2(B0.y, ee0, acc[s][3]);
                ull ee1 = pack2(e1, e1);
                acc[s][0] = fma2(A1.x, ee1, acc[s][0]);
                acc[s][1] = fma2(A1.y, ee1, acc[s][1]);
                acc[s][2] = fma2(B1.x, ee1, acc[s][2]);
                acc[s][3] = fma2(B1.y, ee1, acc[s][3]);
            }
        }
    } else {
        // General path (arbitrary sigma): per-channel exponent, all 4 m's.
        float k2[C_];
#pragma unroll
        for (int c = 0; c < C_; c++) {
            float s = expf(sigma[c]);
            k2[c] = -(0.5f * LOG2E) / (s * s);
        }
        float accs[4][C_];
#pragma unroll
        for (int s = 0; s < 4; s++)
#pragma unroll
            for (int c = 0; c < C_; c++) accs[s][c] = 0.0f;

        for (int jj = 0; jj < PAIRS_W_; jj++) {
            const int P = Pb + jj;
            ulonglong2 v = sxq[P];
            float xv2[2]; unpack2(v.x, xv2[0], xv2[1]);
#pragma unroll
            for (int h = 0; h < 2; h++) {
                ulonglong2 ya = syA[2 * P + h], yb = syB[2 * P + h];
                float yv[C_];
                unpack2(ya.x, yv[0], yv[1]);
                unpack2(ya.y, yv[2], yv[3]);
                unpack2(yb.x, yv[4], yv[5]);
                unpack2(yb.y, yv[6], yv[7]);
#pragma unroll
                for (int s = 0; s < 4; s++) {
                    float dd = xv2[h] - tm[s];
                    float dd2 = dd * dd;
#pragma unroll
                    for (int c = 0; c < C_; c++)
                        accs[s][c] = fmaf(yv[c], ex2f(k2[c] * dd2), accs[s][c]);
                }
            }
        }
#pragma unroll
        for (int s = 0; s < 4; s++)
#pragma unroll
            for (int k = 0; k < 4; k++)
                acc[s][k] = pack2(accs[s][2 * k], accs[s][2 * k + 1]);
    }

    // ---- Log2 warp-tree reduction over the 16 n-chunk partials ----
    // Each thread holds 8 ull2 (16 ull) of partials; slot index = warp id.
#pragma unroll
    for (int step = 8; step >= 1; step >>= 1) {
        __syncthreads();
        if (wrp >= step && wrp < 2 * step) {
            ulonglong2* d2 = sacc + ((wrp - step) * 32 + lane) * 8;
#pragma unroll
            for (int s = 0; s < 4; s++) {
                d2[2 * s]     = make_ulonglong2(acc[s][0], acc[s][1]);
                d2[2 * s + 1] = make_ulonglong2(acc[s][2], acc[s][3]);
            }
        }
        __syncthreads();
        if (wrp < step) {
            const ulonglong2* s2 = sacc + (wrp * 32 + lane) * 8;
#pragma unroll
            for (int s = 0; s < 4; s++) {
                ulonglong2 r0 = s2[2 * s], r1 = s2[2 * s + 1];
                acc[s][0] = add2(acc[s][0], r0.x);
                acc[s][1] = add2(acc[s][1], r0.y);
                acc[s][2] = add2(acc[s][2], r1.x);
                acc[s][3] = add2(acc[s][3], r1.y);
            }
        }
    }

    // Warp 0 publishes final aggs: m-index (s*32+lane) -> 32B of channels.
    __syncthreads();
    if (wrp == 0) {
#pragma unroll
        for (int s = 0; s < 4; s++) {
            ulonglong2* d2 = sacc + (s * 32 + lane) * 2;
            d2[0] = make_ulonglong2(acc[s][0], acc[s][1]);
            d2[1] = make_ulonglong2(acc[s][2], acc[s][3]);
        }
    }
    __syncthreads();

    // ---- Fused epilogue: threads 0..127, one m each ----
    if (tid < TM_) {
        const ulonglong2* s2 = sacc + tid * 2;
        ulonglong2 r0 = s2[0], r1 = s2[1];
        float a[C_];
        unpack2(r0.x, a[0], a[1]);
        unpack2(r0.y, a[2], a[3]);
        unpack2(r1.x, a[4], a[5]);
        unpack2(r1.y, a[6], a[7]);

        float density = a[0];
        float inv = 1.0f / (density + EPS_);
        float feats[C_];
        feats[0] = density;
#pragma unroll
        for (int c = 1; c < C_; c++) feats[c] = a[c] * inv;

        const int m = m0 + tid;
        float* op = out + ((size_t)(b * M_ + m)) * COUT_;
#pragma unroll
        for (int og = 0; og < 4; og++) {
            float rr[4];
#pragma unroll
            for (int k = 0; k < 4; k++) {
                const int o = og * 4 + k;
                float sv = sb[o];
#pragma unroll
                for (int c = 0; c < C_; c++)
                    sv = fmaf(sw[o * C_ + c], feats[c], sv);
                rr[k] = sv;
            }
            *(float4*)(op + og * 4) = make_float4(rr[0], rr[1], rr[2], rr[3]);
        }
    }
}

extern "C" void kernel_launch(void* const* d_in, const int* in_sizes, int n_in,
                              void* d_out, int out_size) {
    (void)in_sizes; (void)n_in; (void)out_size;
    const float* x     = (const float*)d_in[0];
    const float* y     = (const float*)d_in[1];
    const float* t     = (const float*)d_in[2];
    const float* sigma = (const float*)d_in[3];
    const float* w     = (const float*)d_in[4];
    const float* bias  = (const float*)d_in[5];
    float* out = (float*)d_out;

    dim3 grid(M_ / TM_, B_);
    convdeepset_kernel<<<grid, THREADS_>>>(x, y, t, sigma, w, bias, out);
}

// round 10
// speedup vs baseline: 1.1667x; 1.1667x over previous
#include <cuda_runtime.h>

// Shapes fixed by the problem's setup_inputs.
#define B_     16
#define N_     1024
#define M_     1024
#define CIN_   7
#define C_     8
#define COUT_  16
#define TM_    128    // m-values per block (64 lanes x 2 m)
#define NG_    128    // n's per group (N/8)
#define THREADS_ 512  // 8 n-groups x 64 m-threads
#define EPS_   1e-8f

typedef unsigned long long ull;

__device__ __forceinline__ float ex2f(float v) {
    float r; asm("ex2.approx.f32 %0, %1;" : "=f"(r) : "f"(v)); return r;
}
__device__ __forceinline__ ull pack2(float lo, float hi) {
    ull r; asm("mov.b64 %0, {%1, %2};" : "=l"(r) : "f"(lo), "f"(hi)); return r;
}
__device__ __forceinline__ void unpack2(ull v, float& lo, float& hi) {
    asm("mov.b64 {%0, %1}, %2;" : "=f"(lo), "=f"(hi) : "l"(v));
}
// Packed dual-FMA / dual-ADD (Blackwell f32x2, full dual rate).
__device__ __forceinline__ ull fma2(ull a, ull b, ull c) {
    ull d; asm("fma.rn.f32x2 %0, %1, %2, %3;" : "=l"(d) : "l"(a), "l"(b), "l"(c));
    return d;
}
__device__ __forceinline__ ull add2(ull a, ull b) {
    ull d; asm("add.rn.f32x2 %0, %1, %2;" : "=l"(d) : "l"(a), "l"(b));
    return d;
}

// Shared memory (static, <48KB), with aliasing:
//   [0,      8192)  sxq:  512 ulonglong2 {x_2p,x_2p+1 | q_2p,q_2p+1}
//   [8192,  24576)  syA:  1024 ulonglong2  {1,y0 | y1,y2}
//   [24576, 40960)  syB:  1024 ulonglong2  {y3,y4 | y5,y6}
//   [0,     28672)  sacc: 7 groups x 64 thr x 2 m x 8 c floats (ALIASES; post-loop)
//   [40960, 41536)  sw (128 floats) + sb (16 floats)
#define SMEM_BYTES (40960 + 576)

__global__ __launch_bounds__(THREADS_, 1)
void convdeepset_kernel(const float* __restrict__ x,     // [B, N]
                        const float* __restrict__ y,     // [B, N, CIN]
                        const float* __restrict__ t,     // [B, M]
                        const float* __restrict__ sigma, // [C]
                        const float* __restrict__ w,     // [COUT, C]
                        const float* __restrict__ bias,  // [COUT]
                        float* __restrict__ out)         // [B, M, COUT]
{
    __shared__ __align__(16) char smem_raw[SMEM_BYTES];
    ulonglong2* sxq  = (ulonglong2*)smem_raw;              // [512]
    ulonglong2* syA  = (ulonglong2*)(smem_raw + 8192);     // [1024]
    ulonglong2* syB  = (ulonglong2*)(smem_raw + 24576);    // [1024]
    float*      sacc = (float*)smem_raw;                   // aliased, post-loop
    float*      sw   = (float*)(smem_raw + 40960);
    float*      sb   = sw + COUT_ * C_;

    const int b   = blockIdx.y;
    const int m0  = blockIdx.x * TM_;
    const int tid = threadIdx.x;
    const int g   = tid >> 6;        // n-group (0..7), 64 threads each
    const int i   = tid & 63;        // m-lane within tile
    const int mA  = m0 + i;          // first m this thread owns
    const int mB  = m0 + 64 + i;     // second m

    if (tid < COUT_ * C_)                sw[tid] = w[tid];
    if (tid >= 128 && tid < 128 + COUT_) sb[tid - 128] = bias[tid - 128];

    // Per-channel exponent coefficient, log2e folded: arg = k2*(x-t)^2
    const float LOG2E = 1.4426950408889634f;
    const float s0 = expf(sigma[0]);
    const float k20 = -(0.5f * LOG2E) / (s0 * s0);
    bool uniform = true;
#pragma unroll
    for (int c = 1; c < C_; c++) {
        float s = expf(sigma[c]);
        uniform &= ((-(0.5f * LOG2E) / (s * s)) == k20);
    }

    const float tmA = t[b * M_ + mA];
    const float tmB = t[b * M_ + mB];
    // k2*(x-t)^2 = (k2*x^2) + U*x + T
    const ull UUA = pack2(-2.0f * k20 * tmA, -2.0f * k20 * tmA);
    const ull TTA = pack2(k20 * tmA * tmA,   k20 * tmA * tmA);
    const ull UUB = pack2(-2.0f * k20 * tmB, -2.0f * k20 * tmB);
    const ull TTB = pack2(k20 * tmB * tmB,   k20 * tmB * tmB);

    const float* xb  = x + b * N_;
    const float* ybp = y + (size_t)b * N_ * CIN_;

    // ---- Cooperative tile load: thread tid owns n-pair p = tid ----
    {
        const int p = tid;
        const float2 xv = ((const float2*)xb)[p];          // {x(2p), x(2p+1)}
        sxq[p] = make_ulonglong2(pack2(xv.x, xv.y),
                                 pack2(k20 * xv.x * xv.x, k20 * xv.y * xv.y));
        // 14 consecutive floats of y as 7 aligned float2 loads
        const float2* y2 = (const float2*)(ybp + (size_t)(2 * p) * CIN_);
        float2 f0 = y2[0], f1 = y2[1], f2 = y2[2], f3 = y2[3];
        float2 f4 = y2[4], f5 = y2[5], f6 = y2[6];
        syA[2 * p]     = make_ulonglong2(pack2(1.0f, f0.x), pack2(f0.y, f1.x));
        syB[2 * p]     = make_ulonglong2(pack2(f1.y, f2.x), pack2(f2.y, f3.x));
        syA[2 * p + 1] = make_ulonglong2(pack2(1.0f, f3.y), pack2(f4.x, f4.y));
        syB[2 * p + 1] = make_ulonglong2(pack2(f5.x, f5.y), pack2(f6.x, f6.y));
    }
    __syncthreads();

    // Accumulators: [m(2)][channel-pair(4)]
    ull aA0 = 0, aA1 = 0, aA2 = 0, aA3 = 0;
    ull aB0 = 0, aB1 = 0, aB2 = 0, aB3 = 0;

    const ulonglong2* xq = sxq + g * (NG_ / 2);
    const ulonglong2* yA = syA + g * NG_;
    const ulonglong2* yB = syB + g * NG_;

    if (uniform) {
        // ---- Software-pipelined mainloop ----
        // Stage 0: tile + exps for jj=0
        ulonglong2 v  = xq[0];
        ulonglong2 A0 = yA[0], Bv0 = yB[0], A1 = yA[1], Bv1 = yB[1];
        ull eeA0, eeA1, eeB0, eeB1;
        {
            ull argsA = add2(fma2(UUA, v.x, TTA), v.y);
            ull argsB = add2(fma2(UUB, v.x, TTB), v.y);
            float fA0, fA1, fB0, fB1;
            unpack2(argsA, fA0, fA1);
            unpack2(argsB, fB0, fB1);
            float eA0 = ex2f(fA0), eA1 = ex2f(fA1);
            float eB0 = ex2f(fB0), eB1 = ex2f(fB1);
            eeA0 = pack2(eA0, eA0); eeA1 = pack2(eA1, eA1);
            eeB0 = pack2(eB0, eB0); eeB1 = pack2(eB1, eB1);
        }
#pragma unroll 2
        for (int jj = 0; jj < NG_ / 2 - 1; jj++) {
            // Prefetch next tile (latency covered by the accumulate below).
            ulonglong2 vn  = xq[jj + 1];
            ulonglong2 A0n = yA[2 * jj + 2], B0n = yB[2 * jj + 2];
            ulonglong2 A1n = yA[2 * jj + 3], B1n = yB[2 * jj + 3];

            // Accumulate current (16 fma2 ≈ 32 pipe-cycles).
            aA0 = fma2(A0.x,  eeA0, aA0);
            aA1 = fma2(A0.y,  eeA0, aA1);
            aA2 = fma2(Bv0.x, eeA0, aA2);
            aA3 = fma2(Bv0.y, eeA0, aA3);
            aB0 = fma2(A0.x,  eeB0, aB0);
            aB1 = fma2(A0.y,  eeB0, aB1);
            aB2 = fma2(Bv0.x, eeB0, aB2);
            aB3 = fma2(Bv0.y, eeB0, aB3);
            aA0 = fma2(A1.x,  eeA1, aA0);
            aA1 = fma2(A1.y,  eeA1, aA1);
            aA2 = fma2(Bv1.x, eeA1, aA2);
            aA3 = fma2(Bv1.y, eeA1, aA3);
            aB0 = fma2(A1.x,  eeB1, aB0);
            aB1 = fma2(A1.y,  eeB1, aB1);
            aB2 = fma2(Bv1.x, eeB1, aB2);
            aB3 = fma2(Bv1.y, eeB1, aB3);

            // Compute next exps (ex2 latency resolves during next accumulate).
            ull argsA = add2(fma2(UUA, vn.x, TTA), vn.y);
            ull argsB = add2(fma2(UUB, vn.x, TTB), vn.y);
            float fA0, fA1, fB0, fB1;
            unpack2(argsA, fA0, fA1);
            unpack2(argsB, fB0, fB1);
            float eA0 = ex2f(fA0), eA1 = ex2f(fA1);
            float eB0 = ex2f(fB0), eB1 = ex2f(fB1);
            eeA0 = pack2(eA0, eA0); eeA1 = pack2(eA1, eA1);
            eeB0 = pack2(eB0, eB0); eeB1 = pack2(eB1, eB1);

            // Rotate tile buffers.
            v = vn; A0 = A0n; Bv0 = B0n; A1 = A1n; Bv1 = B1n;
        }
        // Tail: accumulate last tile.
        aA0 = fma2(A0.x,  eeA0, aA0);
        aA1 = fma2(A0.y,  eeA0, aA1);
        aA2 = fma2(Bv0.x, eeA0, aA2);
        aA3 = fma2(Bv0.y, eeA0, aA3);
        aB0 = fma2(A0.x,  eeB0, aB0);
        aB1 = fma2(A0.y,  eeB0, aB1);
        aB2 = fma2(Bv0.x, eeB0, aB2);
        aB3 = fma2(Bv0.y, eeB0, aB3);
        aA0 = fma2(A1.x,  eeA1, aA0);
        aA1 = fma2(A1.y,  eeA1, aA1);
        aA2 = fma2(Bv1.x, eeA1, aA2);
        aA3 = fma2(Bv1.y, eeA1, aA3);
        aB0 = fma2(A1.x,  eeB1, aB0);
        aB1 = fma2(A1.y,  eeB1, aB1);
        aB2 = fma2(Bv1.x, eeB1, aB2);
        aB3 = fma2(Bv1.y, eeB1, aB3);
    } else {
        // General path (arbitrary sigma): per-channel exponent, both m's.
        float k2[C_];
#pragma unroll
        for (int c = 0; c < C_; c++) {
            float s = expf(sigma[c]);
            k2[c] = -(0.5f * LOG2E) / (s * s);
        }
        float accsA[C_], accsB[C_];
#pragma unroll
        for (int c = 0; c < C_; c++) { accsA[c] = 0.0f; accsB[c] = 0.0f; }
        for (int jj = 0; jj < NG_ / 2; jj++) {
            ulonglong2 v = sxq[g * (NG_ / 2) + jj];
            float xv2[2]; unpack2(v.x, xv2[0], xv2[1]);
#pragma unroll
            for (int h = 0; h < 2; h++) {
                ulonglong2 ya = yA[2 * jj + h], yb = yB[2 * jj + h];
                float yv[C_];
                unpack2(ya.x, yv[0], yv[1]);
                unpack2(ya.y, yv[2], yv[3]);
                unpack2(yb.x, yv[4], yv[5]);
                unpack2(yb.y, yv[6], yv[7]);
                const float dA = xv2[h] - tmA, dA2 = dA * dA;
                const float dB = xv2[h] - tmB, dB2 = dB * dB;
#pragma unroll
                for (int c = 0; c < C_; c++) {
                    accsA[c] = fmaf(yv[c], ex2f(k2[c] * dA2), accsA[c]);
                    accsB[c] = fmaf(yv[c], ex2f(k2[c] * dB2), accsB[c]);
                }
            }
        }
        aA0 = pack2(accsA[0], accsA[1]);
        aA1 = pack2(accsA[2], accsA[3]);
        aA2 = pack2(accsA[4], accsA[5]);
        aA3 = pack2(accsA[6], accsA[7]);
        aB0 = pack2(accsB[0], accsB[1]);
        aB1 = pack2(accsB[2], accsB[3]);
        aB2 = pack2(accsB[4], accsB[5]);
        aB3 = pack2(accsB[6], accsB[7]);
    }

    // ---- Reduce the 8 group partials (sacc aliases the dead tile) ----
    __syncthreads();
    if (g > 0) {
        ulonglong2* d2 = (ulonglong2*)(sacc + (((g - 1) * 64 + i) * 2) * C_);
        d2[0] = make_ulonglong2(aA0, aA1);
        d2[1] = make_ulonglong2(aA2, aA3);
        d2[2] = make_ulonglong2(aB0, aB1);
        d2[3] = make_ulonglong2(aB2, aB3);
    }
    __syncthreads();
    if (g == 0) {
#pragma unroll
        for (int p = 0; p < 7; p++) {
            const ulonglong2* s2 =
                (const ulonglong2*)(sacc + ((p * 64 + i) * 2) * C_);
            ulonglong2 r0 = s2[0], r1 = s2[1], r2 = s2[2], r3 = s2[3];
            aA0 = add2(aA0, r0.x);
            aA1 = add2(aA1, r0.y);
            aA2 = add2(aA2, r1.x);
            aA3 = add2(aA3, r1.y);
            aB0 = add2(aB0, r2.x);
            aB1 = add2(aB1, r2.y);
            aB2 = add2(aB2, r3.x);
            aB3 = add2(aB3, r3.y);
        }

        // Fused epilogue for both m's.
#pragma unroll
        for (int s = 0; s < 2; s++) {
            float a[C_];
            if (s == 0) {
                unpack2(aA0, a[0], a[1]); unpack2(aA1, a[2], a[3]);
                unpack2(aA2, a[4], a[5]); unpack2(aA3, a[6], a[7]);
            } else {
                unpack2(aB0, a[0], a[1]); unpack2(aB1, a[2], a[3]);
                unpack2(aB2, a[4], a[5]); unpack2(aB3, a[6], a[7]);
            }
            float density = a[0];
            float inv = 1.0f / (density + EPS_);
            float feats[C_];
            feats[0] = density;
#pragma unroll
            for (int c = 1; c < C_; c++) feats[c] = a[c] * inv;

            const int m = s ? mB : mA;
            float* op = out + ((size_t)(b * M_ + m)) * COUT_;
#pragma unroll
            for (int og = 0; og < 4; og++) {
                float rr[4];
#pragma unroll
                for (int k = 0; k < 4; k++) {
                    const int o = og * 4 + k;
                    float sv = sb[o];
#pragma unroll
                    for (int c = 0; c < C_; c++)
                        sv = fmaf(sw[o * C_ + c], feats[c], sv);
                    rr[k] = sv;
                }
                *(float4*)(op + og * 4) = make_float4(rr[0], rr[1], rr[2], rr[3]);
            }
        }
    }
}

extern "C" void kernel_launch(void* const* d_in, const int* in_sizes, int n_in,
                              void* d_out, int out_size) {
    (void)in_sizes; (void)n_in; (void)out_size;
    const float* x     = (const float*)d_in[0];
    const float* y     = (const float*)d_in[1];
    const float* t     = (const float*)d_in[2];
    const float* sigma = (const float*)d_in[3];
    const float* w     = (const float*)d_in[4];
    const float* bias  = (const float*)d_in[5];
    float* out = (float*)d_out;

    dim3 grid(M_ / TM_, B_);
    convdeepset_kernel<<<grid, THREADS_>>>(x, y, t, sigma, w, bias, out);
}

// round 12
// speedup vs baseline: 1.4706x; 1.2605x over previous
#include <cuda_runtime.h>
#include <cstdint>

// Shapes fixed by the problem's setup_inputs.
#define B_      16
#define N_      1024
#define M_      1024
#define CIN_    7
#define C_      8
#define COUT_   16
#define TM_     128     // m-rows per block
#define THREADS_ 512    // 16 warps: 8 m-subtiles x 2 K-halves
#define NSTEP_  32      // k16-steps per K-half (512 n's)
#define EPS_    1e-8f

typedef unsigned long long ull;
typedef unsigned int u32;

// ---------------- smem layout (static, ~41.5KB) ----------------
//   [0,     8192)  sxq: 512 x {x0,x1 | q0,q1} (n-pairs)   [mainloop]
//   [8192, 24576)  bhi: 64 steps x 32 lanes x uint2 (bf16x2 B-frags, hi)
//   [24576,40960)  blo: same, lo residual
//   [40960,41472)  sw  (128 floats)
//   [41472,41536)  sb  (16 floats)
//   aliases after mainloop:
//   [0,     4096)  kred: warps 8..15 D-fragment scratch (8 x 32 x float4)
//   [4096,  8192)  dsc:  final agg [128 m][8 c] f32
#define OFF_SXQ  0
#define OFF_BHI  8192
#define OFF_BLO  24576
#define OFF_SW   40960
#define OFF_SB   41472
#define SMEM_BYTES 41536
#define OFF_KRED 0
#define OFF_DSC  4096

// ---------------- helpers ----------------
__device__ __forceinline__ float ex2f(float v) {
    float r; asm("ex2.approx.f32 %0, %1;" : "=f"(r) : "f"(v)); return r;
}
__device__ __forceinline__ ull pack2(float lo, float hi) {
    ull r; asm("mov.b64 %0, {%1, %2};" : "=l"(r) : "f"(lo), "f"(hi)); return r;
}
__device__ __forceinline__ void unpack2(ull v, float& lo, float& hi) {
    asm("mov.b64 {%0, %1}, %2;" : "=f"(lo), "=f"(hi) : "l"(v));
}
__device__ __forceinline__ ull fma2(ull a, ull b, ull c) {
    ull d; asm("fma.rn.f32x2 %0, %1, %2, %3;" : "=l"(d) : "l"(a), "l"(b), "l"(c));
    return d;
}
__device__ __forceinline__ ull add2(ull a, ull b) {
    ull d; asm("add.rn.f32x2 %0, %1, %2;" : "=l"(d) : "l"(a), "l"(b));
    return d;
}
// pack two f32 into bf16x2: 'lo' -> bits[15:0], 'hi' -> bits[31:16]
__device__ __forceinline__ u32 cvt_bf16x2(float lo, float hi) {
    u32 r; asm("cvt.rn.bf16x2.f32 %0, %1, %2;" : "=r"(r) : "f"(hi), "f"(lo));
    return r;
}
// residual frag: given f32 pair (e0,e1) and their bf16x2 'hi' reg, build lo reg
__device__ __forceinline__ u32 lo_frag(float e0, float e1, u32 hi) {
    float h0 = __uint_as_float(hi << 16);
    float h1 = __uint_as_float(hi & 0xFFFF0000u);
    return cvt_bf16x2(e0 - h0, e1 - h1);
}
// warp-level bf16 MMA: D(16x8,f32) += A(16x16) * B(16x8)
__device__ __forceinline__ void mma_bf16(float& d0, float& d1, float& d2, float& d3,
                                         u32 a0, u32 a1, u32 a2, u32 a3,
                                         u32 b0, u32 b1) {
    asm volatile(
        "mma.sync.aligned.m16n8k16.row.col.f32.bf16.bf16.f32 "
        "{%0,%1,%2,%3}, {%4,%5,%6,%7}, {%8,%9}, {%0,%1,%2,%3};"
        : "+f"(d0), "+f"(d1), "+f"(d2), "+f"(d3)
        : "r"(a0), "r"(a1), "r"(a2), "r"(a3), "r"(b0), "r"(b1));
}

// Fused epilogue for one m: agg -> 16 outputs.
__device__ __forceinline__ void epilogue(const float* a, const float* sw,
                                         const float* sb, float* op) {
    float density = a[0];
    float inv = 1.0f / (density + EPS_);
    float feats[C_];
    feats[0] = density;
#pragma unroll
    for (int c = 1; c < C_; c++) feats[c] = a[c] * inv;
#pragma unroll
    for (int og = 0; og < 4; og++) {
        float rr[4];
#pragma unroll
        for (int k = 0; k < 4; k++) {
            const int o = og * 4 + k;
            float sv = sb[o];
#pragma unroll
            for (int c = 0; c < C_; c++)
                sv = fmaf(sw[o * C_ + c], feats[c], sv);
            rr[k] = sv;
        }
        *(float4*)(op + og * 4) = make_float4(rr[0], rr[1], rr[2], rr[3]);
    }
}

__global__ __launch_bounds__(THREADS_, 1)
void convdeepset_kernel(const float* __restrict__ x,     // [B, N]
                        const float* __restrict__ y,     // [B, N, CIN]
                        const float* __restrict__ t,     // [B, M]
                        const float* __restrict__ sigma, // [C]
                        const float* __restrict__ w,     // [COUT, C]
                        const float* __restrict__ bias,  // [COUT]
                        float* __restrict__ out)         // [B, M, COUT]
{
    __shared__ __align__(16) char smem_raw[SMEM_BYTES];
    ulonglong2* sxq = (ulonglong2*)(smem_raw + OFF_SXQ);   // [512]
    uint2*      bhi = (uint2*)(smem_raw + OFF_BHI);        // [64*32]
    uint2*      blo = (uint2*)(smem_raw + OFF_BLO);        // [64*32]
    float*      sw  = (float*)(smem_raw + OFF_SW);
    float*      sb  = (float*)(smem_raw + OFF_SB);

    const int b    = blockIdx.y;
    const int m0   = blockIdx.x * TM_;
    const int tid  = threadIdx.x;
    const int wrp  = tid >> 5;
    const int lane = tid & 31;
    const int g    = lane >> 2;   // fragment group row / B column (channel)
    const int tt   = lane & 3;    // fragment k-pair selector

    if (tid < COUT_ * C_)                sw[tid] = w[tid];
    if (tid >= 128 && tid < 128 + COUT_) sb[tid - 128] = bias[tid - 128];

    const float LOG2E = 1.4426950408889634f;
    const float s0  = expf(sigma[0]);
    const float k20 = -(0.5f * LOG2E) / (s0 * s0);
    bool uniform = true;
#pragma unroll
    for (int c = 1; c < C_; c++) {
        float s = expf(sigma[c]);
        uniform &= ((-(0.5f * LOG2E) / (s * s)) == k20);
    }

    const float* xb  = x + b * N_;
    const float* ybp = y + (size_t)b * N_ * CIN_;

    if (uniform) {
        // ---- Stage x-pairs {x0,x1 | q0,q1}, q = k20*x^2 ----
        {
            const float2 xv = ((const float2*)xb)[tid];
            sxq[tid] = make_ulonglong2(pack2(xv.x, xv.y),
                                       pack2(k20 * xv.x * xv.x, k20 * xv.y * xv.y));
        }
        // ---- Stage B fragments (Ycat as bf16 hi/lo, mma col-major layout) ----
        // slot (s, lane): b0 = {Ycat[16s+2t][g], Ycat[16s+2t+1][g]},
        //                 b1 = {Ycat[16s+2t+8][g], Ycat[16s+2t+9][g]}
        for (int idx = tid; idx < 64 * 32; idx += THREADS_) {
            const int s  = idx >> 5;
            const int ln = idx & 31;
            const int gg = ln >> 2, ttt = ln & 3;
            const int n0 = s * 16 + 2 * ttt;
            float v00, v01, v10, v11;
            if (gg == 0) {
                v00 = v01 = v10 = v11 = 1.0f;
            } else {
                const float* yp = ybp + (size_t)n0 * CIN_ + (gg - 1);
                v00 = yp[0];
                v01 = yp[CIN_];
                v10 = yp[8 * CIN_];
                v11 = yp[9 * CIN_];
            }
            u32 h0 = cvt_bf16x2(v00, v01);
            u32 h1 = cvt_bf16x2(v10, v11);
            bhi[idx] = make_uint2(h0, h1);
            blo[idx] = make_uint2(lo_frag(v00, v01, h0), lo_frag(v10, v11, h1));
        }
        __syncthreads();

        // ---- Mainloop: warp (wrp&7) owns m-rows, (wrp>>3) owns K-half ----
        const int mw     = (wrp & 7) * 16;       // warp's m-subtile base
        const int kshalf = (wrp >> 3) * NSTEP_;  // first k16-step
        const float tm0 = t[b * M_ + m0 + mw + g];
        const float tm1 = t[b * M_ + m0 + mw + g + 8];
        const ull UU0 = pack2(-2.0f * k20 * tm0, -2.0f * k20 * tm0);
        const ull TT0 = pack2(k20 * tm0 * tm0,   k20 * tm0 * tm0);
        const ull UU1 = pack2(-2.0f * k20 * tm1, -2.0f * k20 * tm1);
        const ull TT1 = pack2(k20 * tm1 * tm1,   k20 * tm1 * tm1);

        float d0 = 0.0f, d1 = 0.0f, d2 = 0.0f, d3 = 0.0f;

#pragma unroll 2
        for (int sl = 0; sl < NSTEP_; sl++) {
            const int s = kshalf + sl;
            // x/q pairs for k = {2t,2t+1} and {2t+8,2t+9}
            const ulonglong2 v0 = sxq[s * 8 + tt];
            const ulonglong2 v1 = sxq[s * 8 + tt + 4];
            // exponent args (packed): arg = U*x + T + q
            ull ga0 = add2(fma2(UU0, v0.x, TT0), v0.y);  // row g,   k pair 0
            ull ga1 = add2(fma2(UU1, v0.x, TT1), v0.y);  // row g+8, k pair 0
            ull ga2 = add2(fma2(UU0, v1.x, TT0), v1.y);  // row g,   k pair 1
            ull ga3 = add2(fma2(UU1, v1.x, TT1), v1.y);  // row g+8, k pair 1
            float e00, e01, e10, e11, e20, e21, e30, e31;
            unpack2(ga0, e00, e01);
            unpack2(ga1, e10, e11);
            unpack2(ga2, e20, e21);
            unpack2(ga3, e30, e31);
            e00 = ex2f(e00); e01 = ex2f(e01);
            e10 = ex2f(e10); e11 = ex2f(e11);
            e20 = ex2f(e20); e21 = ex2f(e21);
            e30 = ex2f(e30); e31 = ex2f(e31);
            // A fragments (hi + lo residual)
            u32 ah0 = cvt_bf16x2(e00, e01);
            u32 ah1 = cvt_bf16x2(e10, e11);
            u32 ah2 = cvt_bf16x2(e20, e21);
            u32 ah3 = cvt_bf16x2(e30, e31);
            u32 al0 = lo_frag(e00, e01, ah0);
            u32 al1 = lo_frag(e10, e11, ah1);
            u32 al2 = lo_frag(e20, e21, ah2);
            u32 al3 = lo_frag(e30, e31, ah3);
            // B fragments
            const uint2 bh = bhi[s * 32 + lane];
            const uint2 bl = blo[s * 32 + lane];
            // D += Ahi*Bhi + Alo*Bhi + Ahi*Blo
            mma_bf16(d0, d1, d2, d3, ah0, ah1, ah2, ah3, bh.x, bh.y);
            mma_bf16(d0, d1, d2, d3, al0, al1, al2, al3, bh.x, bh.y);
            mma_bf16(d0, d1, d2, d3, ah0, ah1, ah2, ah3, bl.x, bl.y);
        }

        // ---- Reduce the two K-halves (scratch aliases dead sxq) ----
        __syncthreads();
        float4* kred = (float4*)(smem_raw + OFF_KRED);
        if (wrp >= 8) kred[(wrp - 8) * 32 + lane] = make_float4(d0, d1, d2, d3);
        __syncthreads();
        float* dsc = (float*)(smem_raw + OFF_DSC);
        if (wrp < 8) {
            const float4 r = kred[wrp * 32 + lane];
            d0 += r.x; d1 += r.y; d2 += r.z; d3 += r.w;
            // D layout: lane holds D[g][2t], D[g][2t+1], D[g+8][2t], D[g+8][2t+1]
            const int ml = mw + g;
            *(float2*)(dsc + ml * C_ + 2 * tt)       = make_float2(d0, d1);
            *(float2*)(dsc + (ml + 8) * C_ + 2 * tt) = make_float2(d2, d3);
        }
        __syncthreads();

        // ---- Fused epilogue: threads 0..127, one m each ----
        if (tid < TM_) {
            float a[C_];
            float4 p0 = *(float4*)(dsc + tid * C_);
            float4 p1 = *(float4*)(dsc + tid * C_ + 4);
            a[0] = p0.x; a[1] = p0.y; a[2] = p0.z; a[3] = p0.w;
            a[4] = p1.x; a[5] = p1.y; a[6] = p1.z; a[7] = p1.w;
            epilogue(a, sw, sb, out + ((size_t)(b * M_ + m0 + tid)) * COUT_);
        }
    } else {
        // ============ general-sigma fallback (correct, cold) ============
        float k2[C_];
#pragma unroll
        for (int c = 0; c < C_; c++) {
            float s = expf(sigma[c]);
            k2[c] = -(0.5f * LOG2E) / (s * s);
        }
        __syncthreads();
        if (tid < TM_) {
            const int m = m0 + tid;
            const float tmv = t[b * M_ + m];
            float a[C_];
#pragma unroll
            for (int c = 0; c < C_; c++) a[c] = 0.0f;
            for (int n = 0; n < N_; n++) {
                const float dd = xb[n] - tmv;
                const float dd2 = dd * dd;
                const float* yp = ybp + (size_t)n * CIN_;
                a[0] += ex2f(k2[0] * dd2);
#pragma unroll
                for (int c = 1; c < C_; c++)
                    a[c] += yp[c - 1] * ex2f(k2[c] * dd2);
            }
            epilogue(a, sw, sb, out + ((size_t)(b * M_ + m)) * COUT_);
        }
    }
}

extern "C" void kernel_launch(void* const* d_in, const int* in_sizes, int n_in,
                              void* d_out, int out_size) {
    (void)in_sizes; (void)n_in; (void)out_size;
    const float* x     = (const float*)d_in[0];
    const float* y     = (const float*)d_in[1];
    const float* t     = (const float*)d_in[2];
    const float* sigma = (const float*)d_in[3];
    const float* w     = (const float*)d_in[4];
    const float* bias  = (const float*)d_in[5];
    float* out = (float*)d_out;

    dim3 grid(M_ / TM_, B_);
    convdeepset_kernel<<<grid, THREADS_>>>(x, y, t, sigma, w, bias, out);
}